// round 4
// baseline (speedup 1.0000x reference)
#include <cuda_runtime.h>
#include <math.h>

#define NSIG 65536
#define NAT  512
#define MDIM 64
#define NBLK 2048            // NSIG / 32 signals per block
#define SMEM_FLOATS (2048 + 2112)
#define SMEM_BYTES  (SMEM_FLOATS * 4)

// ---------------- device globals (scratch; no allocations allowed) ----------
__device__ __align__(16) float  g_dnormJ[MDIM][NAT];   // [m][j]
__device__ __align__(16) float  g_dnormT[NAT][MDIM];   // [j][m]
__device__ __align__(16) float  g_G[NAT][NAT];         // Gram
__device__ double g_partial[NBLK];
__device__ unsigned g_done = 0;

// ---------------- f32x2 packed-FMA helpers (Blackwell) ----------------------
__device__ __forceinline__ unsigned long long fma2(unsigned long long a,
                                                   unsigned long long b,
                                                   unsigned long long c) {
    unsigned long long r;
    asm("fma.rn.f32x2 %0, %1, %2, %3;" : "=l"(r) : "l"(a), "l"(b), "l"(c));
    return r;
}
__device__ __forceinline__ unsigned long long pack2(float x) {
    unsigned long long r;
    asm("mov.b64 %0, {%1, %1};" : "=l"(r) : "f"(x));
    return r;
}
__device__ __forceinline__ float2 unpack2(unsigned long long v) {
    float2 f;
    asm("mov.b64 {%0, %1}, %2;" : "=f"(f.x), "=f"(f.y) : "l"(v));
    return f;
}

// ---------------- K0: normalize dictionary columns --------------------------
__global__ void k_norm(const float* __restrict__ dict) {
    int j = blockIdx.x * blockDim.x + threadIdx.x;
    if (j >= NAT) return;
    float ss = 0.f;
    for (int m = 0; m < MDIM; m++) { float v = dict[m * NAT + j]; ss += v * v; }
    float nrm = fmaxf(sqrtf(ss), 1e-10f);
    for (int m = 0; m < MDIM; m++) {
        float d = dict[m * NAT + j] / nrm;
        g_dnormJ[m][j] = d;
        g_dnormT[j][m] = d;
    }
}

// ---------------- K1: Gram matrix G = Dn^T Dn --------------------------------
__global__ void k_gram() {
    __shared__ float di[MDIM];
    int i = blockIdx.x;
    if (threadIdx.x < MDIM) di[threadIdx.x] = g_dnormT[i][threadIdx.x];
    __syncthreads();
    for (int j = threadIdx.x; j < NAT; j += blockDim.x) {
        float acc = 0.f;
        #pragma unroll
        for (int m = 0; m < MDIM; m++) acc += di[m] * g_dnormJ[m][j];
        g_G[i][j] = acc;
    }
}

// atom index owned by (lane, t):  j = 128*(t>>2) + 4*lane + (t&3)
#define JMAP(lane, t) (128 * ((t) >> 2) + 4 * (lane) + ((t) & 3))

// ---------------- K3: fused zero + GEMM + per-warp OMP + outputs + loss -----
__global__ void __launch_bounds__(256, 2)
k_main(const float* __restrict__ ze, float* __restrict__ out_z,
       float* __restrict__ out_coef, float* __restrict__ out_loss) {
    extern __shared__ float smem[];
    float* sh_x = smem;                    // [64][32]  2048
    float* sh_z = smem + 2048;             // [64][33]  2112 (padded)
    __shared__ double sh_red[256];
    __shared__ int sh_last;

    const int tid  = threadIdx.x;
    const int lane = tid & 31;
    const int wid  = tid >> 5;
    const int tile = blockIdx.x * 32;
    const int b    = tile >> 10;
    const int hw0  = tile & 1023;
    const float* zb = ze + (size_t)b * 65536 + hw0;

    // ---- zero this block's 32 coeff columns (hides under GEMM) ----
    {
        float* cz = out_coef + tile;
        for (int i = tid; i < NAT * 32; i += 256) {
            int j = i >> 5, sl = i & 31;
            cz[(size_t)j * 65536 + sl] = 0.f;
        }
    }

    // ---- load X tile: sh_x[m][sl] (coalesced) ----
    for (int i = tid; i < 2048; i += 256) {
        int m = i >> 5, sl = i & 31;
        sh_x[i] = zb[m * 1024 + sl];
    }
    __syncthreads();

    // ---- Phase 1: h[sig][j] = sum_m dnorm[m][j] * x[m][sig]  (f32x2) ----
    // thread owns signals 4*wid+c, atoms JMAP(lane, t)
    unsigned long long acc[4][8];
    #pragma unroll
    for (int c = 0; c < 4; c++)
        #pragma unroll
        for (int p = 0; p < 8; p++) acc[c][p] = 0ull;

    for (int m = 0; m < MDIM; m++) {
        const ulonglong2* drow = (const ulonglong2*)(&g_dnormJ[m][0]);
        ulonglong2 d0 = drow[lane];
        ulonglong2 d1 = drow[32 + lane];
        ulonglong2 d2 = drow[64 + lane];
        ulonglong2 d3 = drow[96 + lane];
        unsigned long long dv[8] = {d0.x, d0.y, d1.x, d1.y,
                                    d2.x, d2.y, d3.x, d3.y};
        float4 xs4 = *(const float4*)(sh_x + m * 32 + wid * 4);
        float xc[4] = {xs4.x, xs4.y, xs4.z, xs4.w};
        #pragma unroll
        for (int c = 0; c < 4; c++) {
            unsigned long long xp = pack2(xc[c]);
            #pragma unroll
            for (int p = 0; p < 8; p++) acc[c][p] = fma2(dv[p], xp, acc[c][p]);
        }
    }
    // NOTE: acc[c][p] pairs (lo,hi) are atoms t=2p, t=2p+1 under JMAP.

    // ---- Phase 2: per-warp OMP, one owned signal at a time ----
    #pragma unroll 1
    for (int sc = 0; sc < 4; ++sc) {
        const int sl = wid * 4 + sc;
        const int s  = tile + sl;

        float h[16];
        #pragma unroll
        for (int p = 0; p < 8; p++) {
            float2 f = unpack2(acc[sc][p]);
            h[2 * p] = f.x; h[2 * p + 1] = f.y;
        }

        unsigned mask16 = 0u;
        int   idxs[5];
        float xs[5], xsold[5], y[5], rinv[5];
        float Lm[5][5];
        #pragma unroll
        for (int i = 0; i < 5; i++) xsold[i] = 0.f;

        #pragma unroll
        for (int k = 0; k < 5; k++) {
            // ---- masked abs-argmax via redux (first-index tie-break) ----
            unsigned labs = 0u, lj = 0u, lsgn = 0u;
            #pragma unroll
            for (int t = 0; t < 16; t++) {
                if (!((mask16 >> t) & 1u)) {
                    unsigned hb = __float_as_uint(h[t]);
                    unsigned ab = hb & 0x7FFFFFFFu;
                    if (ab > labs) {           // ascending t => smallest j kept
                        labs = ab;
                        lj   = (unsigned)JMAP(lane, t);
                        lsgn = hb >> 31;
                    }
                }
            }
            unsigned wmax = __reduce_max_sync(0xffffffffu, labs);
            unsigned cand = (labs == wmax) ? ((lj << 1) | lsgn) : 0xFFFFFFFFu;
            unsigned kmin = __reduce_min_sync(0xffffffffu, cand);
            int   bestj = (int)(kmin >> 1);
            float absv  = __uint_as_float(wmax);
            float h_sel = (kmin & 1u) ? -absv : absv;
            if (((bestj >> 2) & 31) == lane) {
                int tb = (((bestj >> 7) << 2) | (bestj & 3));
                mask16 |= 1u << tb;
            }
            idxs[k] = bestj;

            // ---- prefetch new Gram row (float4, JMAP layout) ----
            float4 gnew4[4];
            if (k < 4) {
                const float4* gr = (const float4*)(&g_G[bestj][0]);
                #pragma unroll
                for (int q = 0; q < 4; q++)
                    gnew4[q] = __ldg(gr + 32 * q + lane);
            }

            // ---- G_stack scalars via symmetry (same row as gnew fetch) ----
            float gs[4];
            #pragma unroll
            for (int i = 0; i < 4; i++) if (i < k)
                gs[i] = __ldg(&g_G[bestj][idxs[i]]);
            float hbk = h_sel;
            #pragma unroll
            for (int i = 0; i < 4; i++) if (i < k) hbk += xs[i] * gs[i];

            // ---- incremental Cholesky ----
            if (k == 0) {
                Lm[0][0] = 1.f; rinv[0] = 1.f;
            } else {
                float w[4]; float s2 = 0.f;
                #pragma unroll
                for (int i = 0; i < 4; i++) if (i < k) {
                    float v = gs[i];
                    #pragma unroll
                    for (int j2 = 0; j2 < 4; j2++) if (j2 < i) v -= Lm[i][j2] * w[j2];
                    w[i] = v * rinv[i];
                    Lm[k][i] = w[i];
                    s2 += w[i] * w[i];
                }
                Lm[k][k] = sqrtf(1.f - s2);
                rinv[k]  = __frcp_rn(Lm[k][k]);
            }

            // ---- incremental forward solve (y[0..k-1] unchanged) ----
            {
                float v = hbk;
                #pragma unroll
                for (int j2 = 0; j2 < 4; j2++) if (j2 < k) v -= Lm[k][j2] * y[j2];
                y[k] = v * rinv[k];
            }
            // ---- backward solve (size k+1) ----
            #pragma unroll
            for (int i = 4; i >= 0; i--) if (i <= k) {
                float v = y[i];
                #pragma unroll
                for (int j2 = 0; j2 < 5; j2++)
                    if (j2 > i && j2 <= k) v -= Lm[j2][i] * xs[j2];
                xs[i] = v * rinv[i];
            }

            // ---- delta residual update: h -= sum_i dx[i] * G[idxs[i]][:] ----
            if (k < 4) {
                float dx[5];
                #pragma unroll
                for (int i = 0; i < 5; i++) if (i <= k) {
                    dx[i] = xs[i] - xsold[i];
                    xsold[i] = xs[i];
                }
                // rows 0..k-1 reloaded from L1 (float4), row k from gnew4
                #pragma unroll
                for (int i = 0; i < 4; i++) if (i < k) {
                    const float4* gri = (const float4*)(&g_G[idxs[i]][0]);
                    #pragma unroll
                    for (int q = 0; q < 4; q++) {
                        float4 g4 = __ldg(gri + 32 * q + lane);
                        h[4 * q + 0] -= dx[i] * g4.x;
                        h[4 * q + 1] -= dx[i] * g4.y;
                        h[4 * q + 2] -= dx[i] * g4.z;
                        h[4 * q + 3] -= dx[i] * g4.w;
                    }
                }
                #pragma unroll
                for (int q = 0; q < 4; q++) {
                    h[4 * q + 0] -= dx[k] * gnew4[q].x;
                    h[4 * q + 1] -= dx[k] * gnew4[q].y;
                    h[4 * q + 2] -= dx[k] * gnew4[q].z;
                    h[4 * q + 3] -= dx[k] * gnew4[q].w;
                }
            }
        }

        // ---- coeffs scatter (lane i writes atom i) ----
        #pragma unroll
        for (int i = 0; i < 5; i++)
            if (lane == i) out_coef[(size_t)idxs[i] * 65536 + s] = xs[i];

        // ---- sparse reconstruction, staged for coalesced write ----
        float r0 = 0.f, r1 = 0.f;
        #pragma unroll
        for (int i = 0; i < 5; i++) {
            const float* dr = &g_dnormT[idxs[i]][0];
            r0 += xs[i] * dr[lane];
            r1 += xs[i] * dr[lane + 32];
        }
        sh_z[lane * 33 + sl]        = r0;
        sh_z[(lane + 32) * 33 + sl] = r1;
    }
    __syncthreads();

    // ---- Phase 3: coalesced z_dl_st write + deterministic loss reduce ----
    double part = 0.0;
    float* oz = out_z + (size_t)b * 65536 + hw0;
    for (int i = tid; i < 2048; i += 256) {
        int m = i >> 5, sl = i & 31;
        float xv = sh_x[m * 32 + sl];
        float r  = sh_z[m * 33 + sl];
        float dd = r - xv;
        part += (double)dd * (double)dd;
        oz[m * 1024 + sl] = xv + dd;   // z_e + (z_dl - z_e)
    }
    sh_red[tid] = part;
    __syncthreads();
    for (int sft = 128; sft; sft >>= 1) {
        if (tid < sft) sh_red[tid] += sh_red[tid + sft];
        __syncthreads();
    }

    // ---- fused final loss: last block reduces g_partial deterministically ----
    if (tid == 0) {
        g_partial[blockIdx.x] = sh_red[0];
        __threadfence();
        unsigned ticket = atomicAdd(&g_done, 1u);
        sh_last = (ticket == NBLK - 1);
    }
    __syncthreads();
    if (sh_last) {
        double p = 0.0;
        for (int i = tid; i < NBLK; i += 256) p += g_partial[i];
        sh_red[tid] = p;
        __syncthreads();
        for (int sft = 128; sft; sft >>= 1) {
            if (tid < sft) sh_red[tid] += sh_red[tid + sft];
            __syncthreads();
        }
        if (tid == 0) {
            out_loss[0] = (float)(1.25 * sh_red[0] / 4194304.0);
            atomicExch(&g_done, 0u);   // reset for next graph replay
        }
    }
}

// ---------------- launch ------------------------------------------------------
extern "C" void kernel_launch(void* const* d_in, const int* in_sizes, int n_in,
                              void* d_out, int out_size) {
    const float* ze   = (const float*)d_in[0];
    const float* dict = (const float*)d_in[1];
    float* out      = (float*)d_out;
    float* out_z    = out;                 // 4,194,304
    float* out_loss = out + 4194304;       // 1
    float* out_coef = out + 4194305;       // 33,554,432

    cudaFuncSetAttribute(k_main, cudaFuncAttributeMaxDynamicSharedMemorySize,
                         SMEM_BYTES);

    k_norm<<<2, 256>>>(dict);
    k_gram<<<NAT, 128>>>();
    k_main<<<NBLK, 256, SMEM_BYTES>>>(ze, out_z, out_coef, out_loss);
}

// round 5
// speedup vs baseline: 1.5461x; 1.5461x over previous
#include <cuda_runtime.h>
#include <math.h>

#define NSIG 65536
#define NAT  512
#define MDIM 64
#define NBLK 2048            // NSIG / 32 signals per block
#define SMEM_FLOATS (2048 + 16384 + 2112)
#define SMEM_BYTES  (SMEM_FLOATS * 4)

// ---------------- device globals (scratch; no allocations allowed) ----------
__device__ __align__(16) float  g_dnormJ[MDIM][NAT];   // [m][j]
__device__ __align__(16) float  g_dnormT[NAT][MDIM];   // [j][m]
__device__ __align__(16) float  g_G[NAT][NAT];         // Gram
__device__ double g_partial[NBLK];
__device__ unsigned g_done = 0;

// ---------------- f32x2 packed-FMA helpers (Blackwell) ----------------------
__device__ __forceinline__ unsigned long long fma2(unsigned long long a,
                                                   unsigned long long b,
                                                   unsigned long long c) {
    unsigned long long r;
    asm("fma.rn.f32x2 %0, %1, %2, %3;" : "=l"(r) : "l"(a), "l"(b), "l"(c));
    return r;
}
__device__ __forceinline__ unsigned long long pack2(float x) {
    unsigned long long r;
    asm("mov.b64 %0, {%1, %1};" : "=l"(r) : "f"(x));
    return r;
}
__device__ __forceinline__ float2 unpack2(unsigned long long v) {
    float2 f;
    asm("mov.b64 {%0, %1}, %2;" : "=f"(f.x), "=f"(f.y) : "l"(v));
    return f;
}

// ---------------- K0: normalize dictionary columns --------------------------
__global__ void k_norm(const float* __restrict__ dict) {
    int j = blockIdx.x * blockDim.x + threadIdx.x;
    if (j >= NAT) return;
    float s0 = 0.f, s1 = 0.f, s2 = 0.f, s3 = 0.f;
    #pragma unroll
    for (int m = 0; m < MDIM; m += 4) {          // 4 independent chains -> MLP
        float v0 = __ldg(dict + (m + 0) * NAT + j);
        float v1 = __ldg(dict + (m + 1) * NAT + j);
        float v2 = __ldg(dict + (m + 2) * NAT + j);
        float v3 = __ldg(dict + (m + 3) * NAT + j);
        s0 += v0 * v0; s1 += v1 * v1; s2 += v2 * v2; s3 += v3 * v3;
    }
    float nrm  = fmaxf(sqrtf((s0 + s1) + (s2 + s3)), 1e-10f);
    float rn   = 1.f / nrm;
    #pragma unroll 8
    for (int m = 0; m < MDIM; m++) {
        float d = __ldg(dict + m * NAT + j) * rn;
        g_dnormJ[m][j] = d;
        g_dnormT[j][m] = d;
    }
}

// ---------------- K1: Gram matrix G = Dn^T Dn --------------------------------
__global__ void k_gram() {
    __shared__ float di[MDIM];
    int i = blockIdx.x;
    if (threadIdx.x < MDIM) di[threadIdx.x] = g_dnormT[i][threadIdx.x];
    __syncthreads();
    for (int j = threadIdx.x; j < NAT; j += blockDim.x) {
        float acc = 0.f;
        #pragma unroll
        for (int m = 0; m < MDIM; m++) acc += di[m] * g_dnormJ[m][j];
        g_G[i][j] = acc;
    }
}

// atom index owned by (lane, t):  j = 128*(t>>2) + 4*lane + (t&3)
#define JMAP(lane, t) (128 * ((t) >> 2) + 4 * (lane) + ((t) & 3))

// ---------------- K3: fused zero + GEMM + per-warp OMP + outputs + loss -----
__global__ void __launch_bounds__(256, 2)
k_main(const float* __restrict__ ze, float* __restrict__ out_z,
       float* __restrict__ out_coef, float* __restrict__ out_loss) {
    extern __shared__ float smem[];
    float* sh_x = smem;                    // [64][32]        2048
    float* sh_h = smem + 2048;             // [64][256] tp    16384
    float* sh_z = smem + 2048 + 16384;     // [64][33] pad    2112
    __shared__ double sh_red[256];
    __shared__ int sh_last;

    const int tid  = threadIdx.x;
    const int lane = tid & 31;
    const int wid  = tid >> 5;
    const int tile = blockIdx.x * 32;
    const int b    = tile >> 10;
    const int hw0  = tile & 1023;
    const float* zb = ze + (size_t)b * 65536 + hw0;

    // ---- zero this block's 32 coeff columns (hides under GEMM) ----
    {
        float* cz = out_coef + tile;
        for (int i = tid; i < NAT * 32; i += 256) {
            int j = i >> 5, sl = i & 31;
            cz[(size_t)j * 65536 + sl] = 0.f;
        }
    }

    // ---- load X tile: sh_x[m][sl] (coalesced) ----
    for (int i = tid; i < 2048; i += 256) {
        int m = i >> 5, sl = i & 31;
        sh_x[i] = zb[m * 1024 + sl];
    }
    __syncthreads();

    // ---- Phase 1: h[sig][j] = sum_m dnorm[m][j] * x[m][sig]  (f32x2) ----
    // thread owns signals 4*wid+c, atoms JMAP(lane, t); stage results to
    // thread-private smem slots (stride-256, conflict-free) so the 64-reg
    // accumulator block dies here (NO runtime-indexed register arrays!)
    {
        unsigned long long acc[4][8];
        #pragma unroll
        for (int c = 0; c < 4; c++)
            #pragma unroll
            for (int p = 0; p < 8; p++) acc[c][p] = 0ull;

        for (int m = 0; m < MDIM; m++) {
            const ulonglong2* drow = (const ulonglong2*)(&g_dnormJ[m][0]);
            ulonglong2 d0 = drow[lane];
            ulonglong2 d1 = drow[32 + lane];
            ulonglong2 d2 = drow[64 + lane];
            ulonglong2 d3 = drow[96 + lane];
            unsigned long long dv[8] = {d0.x, d0.y, d1.x, d1.y,
                                        d2.x, d2.y, d3.x, d3.y};
            float4 xs4 = *(const float4*)(sh_x + m * 32 + wid * 4);
            float xc[4] = {xs4.x, xs4.y, xs4.z, xs4.w};
            #pragma unroll
            for (int c = 0; c < 4; c++) {
                unsigned long long xp = pack2(xc[c]);
                #pragma unroll
                for (int p = 0; p < 8; p++) acc[c][p] = fma2(dv[p], xp, acc[c][p]);
            }
        }
        #pragma unroll
        for (int c = 0; c < 4; c++)
            #pragma unroll
            for (int p = 0; p < 8; p++) {
                float2 f = unpack2(acc[c][p]);
                sh_h[(c * 16 + 2 * p + 0) * 256 + tid] = f.x;
                sh_h[(c * 16 + 2 * p + 1) * 256 + tid] = f.y;
            }
    }
    // thread-private staging: no __syncthreads needed

    // ---- Phase 2: per-warp OMP, one owned signal at a time ----
    #pragma unroll 1
    for (int sc = 0; sc < 4; ++sc) {
        const int sl = wid * 4 + sc;
        const int s  = tile + sl;

        float h[16];
        #pragma unroll
        for (int t = 0; t < 16; t++) h[t] = sh_h[(sc * 16 + t) * 256 + tid];

        unsigned mask16 = 0u;
        int   idxs[5];
        float xs[5], xsold[5], y[5], rinv[5];
        float Lm[5][5];
        #pragma unroll
        for (int i = 0; i < 5; i++) xsold[i] = 0.f;

        #pragma unroll
        for (int k = 0; k < 5; k++) {
            // ---- masked abs-argmax via redux (first-index tie-break) ----
            unsigned labs = 0u, lj = 0u, lsgn = 0u;
            #pragma unroll
            for (int t = 0; t < 16; t++) {
                if (!((mask16 >> t) & 1u)) {
                    unsigned hb = __float_as_uint(h[t]);
                    unsigned ab = hb & 0x7FFFFFFFu;
                    if (ab > labs) {           // ascending t => smallest j kept
                        labs = ab;
                        lj   = (unsigned)JMAP(lane, t);
                        lsgn = hb >> 31;
                    }
                }
            }
            unsigned wmax = __reduce_max_sync(0xffffffffu, labs);
            unsigned cand = (labs == wmax) ? ((lj << 1) | lsgn) : 0xFFFFFFFFu;
            unsigned kmin = __reduce_min_sync(0xffffffffu, cand);
            int   bestj = (int)(kmin >> 1);
            float absv  = __uint_as_float(wmax);
            float h_sel = (kmin & 1u) ? -absv : absv;
            if (((bestj >> 2) & 31) == lane) {
                int tb = (((bestj >> 7) << 2) | (bestj & 3));
                mask16 |= 1u << tb;
            }
            idxs[k] = bestj;

            // ---- prefetch new Gram row (float4, JMAP layout) ----
            float4 gnew4[4];
            if (k < 4) {
                const float4* gr = (const float4*)(&g_G[bestj][0]);
                #pragma unroll
                for (int q = 0; q < 4; q++)
                    gnew4[q] = __ldg(gr + 32 * q + lane);
            }

            // ---- G_stack scalars via symmetry (same row as gnew fetch) ----
            float gs[4];
            #pragma unroll
            for (int i = 0; i < 4; i++) if (i < k)
                gs[i] = __ldg(&g_G[bestj][idxs[i]]);
            float hbk = h_sel;
            #pragma unroll
            for (int i = 0; i < 4; i++) if (i < k) hbk += xs[i] * gs[i];

            // ---- incremental Cholesky ----
            if (k == 0) {
                Lm[0][0] = 1.f; rinv[0] = 1.f;
            } else {
                float w[4]; float s2 = 0.f;
                #pragma unroll
                for (int i = 0; i < 4; i++) if (i < k) {
                    float v = gs[i];
                    #pragma unroll
                    for (int j2 = 0; j2 < 4; j2++) if (j2 < i) v -= Lm[i][j2] * w[j2];
                    w[i] = v * rinv[i];
                    Lm[k][i] = w[i];
                    s2 += w[i] * w[i];
                }
                Lm[k][k] = sqrtf(1.f - s2);
                rinv[k]  = __frcp_rn(Lm[k][k]);
            }

            // ---- incremental forward solve (y[0..k-1] unchanged) ----
            {
                float v = hbk;
                #pragma unroll
                for (int j2 = 0; j2 < 4; j2++) if (j2 < k) v -= Lm[k][j2] * y[j2];
                y[k] = v * rinv[k];
            }
            // ---- backward solve (size k+1) ----
            #pragma unroll
            for (int i = 4; i >= 0; i--) if (i <= k) {
                float v = y[i];
                #pragma unroll
                for (int j2 = 0; j2 < 5; j2++)
                    if (j2 > i && j2 <= k) v -= Lm[j2][i] * xs[j2];
                xs[i] = v * rinv[i];
            }

            // ---- delta residual update: h -= sum_i dx[i] * G[idxs[i]][:] ----
            if (k < 4) {
                float dx[5];
                #pragma unroll
                for (int i = 0; i < 5; i++) if (i <= k) {
                    dx[i] = xs[i] - xsold[i];
                    xsold[i] = xs[i];
                }
                // rows 0..k-1 reloaded from L1 (float4), row k from gnew4
                #pragma unroll
                for (int i = 0; i < 4; i++) if (i < k) {
                    const float4* gri = (const float4*)(&g_G[idxs[i]][0]);
                    #pragma unroll
                    for (int q = 0; q < 4; q++) {
                        float4 g4 = __ldg(gri + 32 * q + lane);
                        h[4 * q + 0] -= dx[i] * g4.x;
                        h[4 * q + 1] -= dx[i] * g4.y;
                        h[4 * q + 2] -= dx[i] * g4.z;
                        h[4 * q + 3] -= dx[i] * g4.w;
                    }
                }
                #pragma unroll
                for (int q = 0; q < 4; q++) {
                    h[4 * q + 0] -= dx[k] * gnew4[q].x;
                    h[4 * q + 1] -= dx[k] * gnew4[q].y;
                    h[4 * q + 2] -= dx[k] * gnew4[q].z;
                    h[4 * q + 3] -= dx[k] * gnew4[q].w;
                }
            }
        }

        // ---- coeffs scatter (lane i writes atom i) ----
        #pragma unroll
        for (int i = 0; i < 5; i++)
            if (lane == i) out_coef[(size_t)idxs[i] * 65536 + s] = xs[i];

        // ---- sparse reconstruction, staged for coalesced write ----
        float r0 = 0.f, r1 = 0.f;
        #pragma unroll
        for (int i = 0; i < 5; i++) {
            const float* dr = &g_dnormT[idxs[i]][0];
            r0 += xs[i] * dr[lane];
            r1 += xs[i] * dr[lane + 32];
        }
        sh_z[lane * 33 + sl]        = r0;
        sh_z[(lane + 32) * 33 + sl] = r1;
    }
    __syncthreads();

    // ---- Phase 3: coalesced z_dl_st write + deterministic loss reduce ----
    double part = 0.0;
    float* oz = out_z + (size_t)b * 65536 + hw0;
    for (int i = tid; i < 2048; i += 256) {
        int m = i >> 5, sl = i & 31;
        float xv = sh_x[m * 32 + sl];
        float r  = sh_z[m * 33 + sl];
        float dd = r - xv;
        part += (double)dd * (double)dd;
        oz[m * 1024 + sl] = xv + dd;   // z_e + (z_dl - z_e)
    }
    sh_red[tid] = part;
    __syncthreads();
    for (int sft = 128; sft; sft >>= 1) {
        if (tid < sft) sh_red[tid] += sh_red[tid + sft];
        __syncthreads();
    }

    // ---- fused final loss: last block reduces g_partial deterministically ----
    if (tid == 0) {
        g_partial[blockIdx.x] = sh_red[0];
        __threadfence();
        unsigned ticket = atomicAdd(&g_done, 1u);
        sh_last = (ticket == NBLK - 1);
    }
    __syncthreads();
    if (sh_last) {
        double p = 0.0;
        for (int i = tid; i < NBLK; i += 256) p += g_partial[i];
        sh_red[tid] = p;
        __syncthreads();
        for (int sft = 128; sft; sft >>= 1) {
            if (tid < sft) sh_red[tid] += sh_red[tid + sft];
            __syncthreads();
        }
        if (tid == 0) {
            out_loss[0] = (float)(1.25 * sh_red[0] / 4194304.0);
            atomicExch(&g_done, 0u);   // reset for next graph replay
        }
    }
}

// ---------------- launch ------------------------------------------------------
extern "C" void kernel_launch(void* const* d_in, const int* in_sizes, int n_in,
                              void* d_out, int out_size) {
    const float* ze   = (const float*)d_in[0];
    const float* dict = (const float*)d_in[1];
    float* out      = (float*)d_out;
    float* out_z    = out;                 // 4,194,304
    float* out_loss = out + 4194304;       // 1
    float* out_coef = out + 4194305;       // 33,554,432

    cudaFuncSetAttribute(k_main, cudaFuncAttributeMaxDynamicSharedMemorySize,
                         SMEM_BYTES);

    k_norm<<<2, 256>>>(dict);
    k_gram<<<NAT, 128>>>();
    k_main<<<NBLK, 256, SMEM_BYTES>>>(ze, out_z, out_coef, out_loss);
}